// round 15
// baseline (speedup 1.0000x reference)
#include <cuda_runtime.h>
#include <cuda_fp16.h>
#include <math.h>
#include <stdint.h>

// Problem shape (fixed by the reference)
#define BQ 64
#define SQ 197
#define DQ 768
#define HQ 3072
#define MQ (BQ * SQ)  // 12608 = 197 * 64  -> M-tiles of 64 are EXACT (no edge)

// ---------------------------------------------------------------------------
// Device global scratch (no allocation allowed)
// ---------------------------------------------------------------------------
__device__ __half g_xh [(size_t)MQ * DQ];   // x in fp16
__device__ __half g_hh [(size_t)MQ * HQ];   // h (post-GELU) in fp16
__device__ __half g_q1 [(size_t)HQ * DQ];   // ternary w1 in fp16 (exact)
__device__ __half g_q2 [(size_t)DQ * HQ];   // ternary w2 in fp16 (exact)
__device__ float g_partial[1024];
__device__ float g_gamma[2];

__device__ __forceinline__ uint32_t smem_u32(const void* p) {
    uint32_t a;
    asm("{ .reg .u64 t; cvta.to.shared.u64 t, %1; cvt.u32.u64 %0, t; }"
        : "=r"(a) : "l"(p));
    return a;
}

__device__ __forceinline__ uint32_t pack_h2(float a, float b) {
    __half2 p;
    p.x = __float2half_rn(a);
    p.y = __float2half_rn(b);
    return *(uint32_t*)&p;
}

// ---------------------------------------------------------------------------
// prep1: blocks 0-511 abs(w1), 512-1023 abs(w2), rest cvt x (MLP=4).
// ---------------------------------------------------------------------------
__global__ void prep1_kernel(const float* __restrict__ w1,
                             const float* __restrict__ w2, int nw,
                             const float* __restrict__ x,
                             __half* __restrict__ xh, int nx4) {
    int b = blockIdx.x;
    if (b < 1024) {
        const float* w = (b < 512) ? w1 : w2;
        int slot = (b < 512) ? 0 : 1;
        int rb = b & 511;
        __shared__ float sdata[256];
        float s = 0.0f;
        for (int i = rb * blockDim.x + threadIdx.x; i < nw;
             i += 512 * blockDim.x)
            s += fabsf(w[i]);
        sdata[threadIdx.x] = s;
        __syncthreads();
        #pragma unroll
        for (int off = 128; off > 0; off >>= 1) {
            if (threadIdx.x < off) sdata[threadIdx.x] += sdata[threadIdx.x + off];
            __syncthreads();
        }
        if (threadIdx.x == 0) g_partial[slot * 512 + rb] = sdata[0];
    } else {
        int base = (b - 1024) * 1024 + threadIdx.x;
        float4 v[4];
        int idx[4];
        #pragma unroll
        for (int u = 0; u < 4; u++) {
            idx[u] = base + u * 256;
            if (idx[u] < nx4) v[u] = ((const float4*)x)[idx[u]];
        }
        #pragma unroll
        for (int u = 0; u < 4; u++) {
            if (idx[u] < nx4) {
                uint2 st = make_uint2(pack_h2(v[u].x, v[u].y),
                                      pack_h2(v[u].z, v[u].w));
                ((uint2*)xh)[idx[u]] = st;
            }
        }
    }
}

__global__ void finalize_gamma_kernel(int n1, int n2) {
    __shared__ float sdata[512];
    int t = threadIdx.x;
    sdata[t] = g_partial[t];
    __syncthreads();
    #pragma unroll
    for (int off = 256; off > 0; off >>= 1) {
        if (t < off) sdata[t] += sdata[t + off];
        __syncthreads();
    }
    if (t == 0) g_gamma[0] = sdata[0] / (float)n1 + 1e-5f;
    __syncthreads();
    sdata[t] = g_partial[512 + t];
    __syncthreads();
    #pragma unroll
    for (int off = 256; off > 0; off >>= 1) {
        if (t < off) sdata[t] += sdata[t + off];
        __syncthreads();
    }
    if (t == 0) g_gamma[1] = sdata[0] / (float)n2 + 1e-5f;
}

// ternarize BOTH weights (MLP=4): blocks [0,576) -> w1, [576,1152) -> w2
__global__ void quant_both_kernel(const float* __restrict__ w1,
                                  __half* __restrict__ q1,
                                  const float* __restrict__ w2,
                                  __half* __restrict__ q2, int n4) {
    int b = blockIdx.x;
    const float* w;
    __half* q;
    int slot, rb;
    if (b < 576) { w = w1; q = q1; slot = 0; rb = b; }
    else         { w = w2; q = q2; slot = 1; rb = b - 576; }
    float inv = 1.0f / g_gamma[slot];
    int base = rb * 1024 + threadIdx.x;
    float4 v[4];
    int idx[4];
    #pragma unroll
    for (int u = 0; u < 4; u++) {
        idx[u] = base + u * 256;
        if (idx[u] < n4) v[u] = ((const float4*)w)[idx[u]];
    }
    #pragma unroll
    for (int u = 0; u < 4; u++) {
        if (idx[u] < n4) {
            float t0 = fminf(1.0f, fmaxf(-1.0f, rintf(v[u].x * inv)));
            float t1 = fminf(1.0f, fmaxf(-1.0f, rintf(v[u].y * inv)));
            float t2 = fminf(1.0f, fmaxf(-1.0f, rintf(v[u].z * inv)));
            float t3 = fminf(1.0f, fmaxf(-1.0f, rintf(v[u].w * inv)));
            uint2 st = make_uint2(pack_h2(t0, t1), pack_h2(t2, t3));
            ((uint2*)q)[idx[u]] = st;
        }
    }
}

// ---------------------------------------------------------------------------
// HMMA GEMM (R13/R14 engine): 64x128 CTA tile, 128 threads (4 warps x 64x32),
// 4 CTAs/SM, analytic swizzle, double-buffered cp.async.
// R15: M % 64 == 0 -> all M-edge predication removed (immediate-size cp.async,
// branch-free epilogue); chunk loop unrolled x2 with compile-time buf offsets.
// ---------------------------------------------------------------------------
template <int GELU_H>
__global__ __launch_bounds__(128, 4)
void hmma_gemm(const __half* __restrict__ A,
               const __half* __restrict__ B,
               const float* __restrict__ bias,
               void* __restrict__ Cout,
               int M, int N, int K, int gslot) {
    extern __shared__ char smem[];
    const uint32_t sb = smem_u32(smem);
    const int tid  = threadIdx.x;
    const int wid  = tid >> 5;      // 0..3 -> n-block of 32
    const int lane = tid & 31;
    const int m0 = blockIdx.y * 64;
    const int n0 = blockIdx.x * 128;
    const int wn = wid;

    const int nch = K >> 6;    // chunks of 64 fp16 (12 or 48 -> even)

    const uint32_t preA = (uint32_t)((((lane >> 4) << 4) ^ ((lane & 7) << 4)));
    const uint32_t preB = (uint32_t)((((lane & 8) << 1) ^ ((lane & 7) << 4)));
    const uint32_t rowA = (uint32_t)(lane & 15) * 128u;
    const uint32_t rowB = (uint32_t)(wn * 32 + (lane & 7) + ((lane >> 4) << 3)) * 128u;

    float acc[4][4][4];
    #pragma unroll
    for (int i = 0; i < 4; i++)
        #pragma unroll
        for (int j = 0; j < 4; j++)
            #pragma unroll
            for (int k = 0; k < 4; k++) acc[i][j][k] = 0.0f;

    // stage BUF: A(8KB) @ BUF*24576, B(16KB) @ +8192  (BUF compile-time)
    auto load_chunk = [&](int c, const uint32_t offA) {
        const uint32_t offB = offA + 8192u;
        const __half* Ag = A + (size_t)m0 * K + (size_t)c * 64;
        const __half* Bg = B + (size_t)n0 * K + (size_t)c * 64;
        #pragma unroll
        for (int t = 0; t < 4; t++) {          // A: 64 rows x 8 sixteens
            int idx = tid + t * 128;
            int row = idx >> 3;
            int c16 = idx & 7;
            uint32_t sw = (uint32_t)row * 128u
                        + (((uint32_t)c16 * 16u) ^ (((uint32_t)row & 7u) << 4));
            const void* ga = Ag + (size_t)row * K + c16 * 8;
            asm volatile("cp.async.cg.shared.global [%0], [%1], 16;"
                         :: "r"(sb + offA + sw), "l"(ga));
        }
        #pragma unroll
        for (int t = 0; t < 8; t++) {          // B: 128 rows x 8 sixteens
            int idx = tid + t * 128;
            int row = idx >> 3;
            int c16 = idx & 7;
            uint32_t sw = (uint32_t)row * 128u
                        + (((uint32_t)c16 * 16u) ^ (((uint32_t)row & 7u) << 4));
            const void* gb = Bg + (size_t)row * K + c16 * 8;
            asm volatile("cp.async.cg.shared.global [%0], [%1], 16;"
                         :: "r"(sb + offB + sw), "l"(gb));
        }
        asm volatile("cp.async.commit_group;" ::: "memory");
    };

    auto compute_chunk = [&](const uint32_t offBuf) {
        const uint32_t baseA = sb + offBuf + rowA;
        const uint32_t baseB = sb + offBuf + 8192u + rowB;
        #pragma unroll
        for (int kk = 0; kk < 64; kk += 16) {
            const uint32_t cA = ((uint32_t)(2 * kk)) ^ preA;
            const uint32_t cB = ((uint32_t)(2 * kk)) ^ preB;
            uint32_t a[4][4];
            #pragma unroll
            for (int mi = 0; mi < 4; mi++) {
                asm volatile(
                    "ldmatrix.sync.aligned.m8n8.x4.shared.b16 {%0,%1,%2,%3}, [%4];"
                    : "=r"(a[mi][0]), "=r"(a[mi][1]), "=r"(a[mi][2]), "=r"(a[mi][3])
                    : "r"(baseA + (uint32_t)(mi * 2048) + cA));
            }
            uint32_t b[4][2];
            #pragma unroll
            for (int nj = 0; nj < 2; nj++) {
                uint32_t b0, b1, b2, b3;
                asm volatile(
                    "ldmatrix.sync.aligned.m8n8.x4.shared.b16 {%0,%1,%2,%3}, [%4];"
                    : "=r"(b0), "=r"(b1), "=r"(b2), "=r"(b3)
                    : "r"(baseB + (uint32_t)(nj * 2048) + cB));
                b[nj * 2 + 0][0] = b0; b[nj * 2 + 0][1] = b1;
                b[nj * 2 + 1][0] = b2; b[nj * 2 + 1][1] = b3;
            }
            #pragma unroll
            for (int mi = 0; mi < 4; mi++)
                #pragma unroll
                for (int ni = 0; ni < 4; ni++)
                    asm volatile(
                        "mma.sync.aligned.m16n8k16.row.col.f32.f16.f16.f32 "
                        "{%0,%1,%2,%3}, {%4,%5,%6,%7}, {%8,%9}, {%0,%1,%2,%3};"
                        : "+f"(acc[mi][ni][0]), "+f"(acc[mi][ni][1]),
                          "+f"(acc[mi][ni][2]), "+f"(acc[mi][ni][3])
                        : "r"(a[mi][0]), "r"(a[mi][1]), "r"(a[mi][2]), "r"(a[mi][3]),
                          "r"(b[ni][0]), "r"(b[ni][1]));
        }
    };

    // 2x-unrolled double-buffered mainloop (nch even: 12 or 48)
    load_chunk(0, 0u);
    for (int c = 0; c < nch; c += 2) {
        // even chunk -> buffer 0
        if (c + 1 < nch) {
            load_chunk(c + 1, 24576u);
            asm volatile("cp.async.wait_group 1;" ::: "memory");
        } else {
            asm volatile("cp.async.wait_group 0;" ::: "memory");
        }
        __syncthreads();
        compute_chunk(0u);
        __syncthreads();
        // odd chunk -> buffer 1
        if (c + 2 < nch) {
            load_chunk(c + 2, 0u);
            asm volatile("cp.async.wait_group 1;" ::: "memory");
        } else {
            asm volatile("cp.async.wait_group 0;" ::: "memory");
        }
        __syncthreads();
        compute_chunk(24576u);
        __syncthreads();
    }

    // ---- epilogue (branch-free: M % 64 == 0) ----
    const float gamma = g_gamma[gslot];
    #pragma unroll
    for (int mi = 0; mi < 4; mi++) {
        #pragma unroll
        for (int half = 0; half < 2; half++) {
            int gr = m0 + mi * 16 + (lane >> 2) + half * 8;
            #pragma unroll
            for (int ni = 0; ni < 4; ni++) {
                int gc = n0 + wn * 32 + ni * 8 + 2 * (lane & 3);
                float v0 = acc[mi][ni][half * 2 + 0] * gamma + bias[gc];
                float v1 = acc[mi][ni][half * 2 + 1] * gamma + bias[gc + 1];
                if (GELU_H) {
                    v0 = 0.5f * v0 * (1.0f + erff(v0 * 0.70710678118654752f));
                    v1 = 0.5f * v1 * (1.0f + erff(v1 * 0.70710678118654752f));
                    __half2 p;
                    p.x = __float2half_rn(v0);
                    p.y = __float2half_rn(v1);
                    *(__half2*)((__half*)Cout + (size_t)gr * N + gc) = p;
                } else {
                    *(float2*)((float*)Cout + (size_t)gr * N + gc) =
                        make_float2(v0, v1);
                }
            }
        }
    }
}

// ---------------------------------------------------------------------------
// Launch
// ---------------------------------------------------------------------------
extern "C" void kernel_launch(void* const* d_in, const int* in_sizes, int n_in,
                              void* d_out, int out_size) {
    const float* x  = (const float*)d_in[0];
    const float* w1 = (const float*)d_in[1];
    const float* b1 = (const float*)d_in[2];
    const float* w2 = (const float*)d_in[3];
    const float* b2 = (const float*)d_in[4];
    float* out = (float*)d_out;

    __half *p_xh, *p_hh, *p_q1, *p_q2;
    cudaGetSymbolAddress((void**)&p_xh, g_xh);
    cudaGetSymbolAddress((void**)&p_hh, g_hh);
    cudaGetSymbolAddress((void**)&p_q1, g_q1);
    cudaGetSymbolAddress((void**)&p_q2, g_q2);

    const int NW = HQ * DQ;          // 2359296
    const int NX4 = MQ * DQ / 4;     // 2420736 = 2364 * 1024
    const int SMEM_DYN = 2 * 24576;  // 48KB

    static bool attr_done = false;
    if (!attr_done) {
        cudaFuncSetAttribute(hmma_gemm<1>,
            cudaFuncAttributeMaxDynamicSharedMemorySize, SMEM_DYN);
        cudaFuncSetAttribute(hmma_gemm<0>,
            cudaFuncAttributeMaxDynamicSharedMemorySize, SMEM_DYN);
        attr_done = true;
    }

    prep1_kernel<<<1024 + NX4 / 1024, 256>>>(w1, w2, NW, x, p_xh, NX4);
    finalize_gamma_kernel<<<1, 512>>>(NW, NW);
    quant_both_kernel<<<1152, 256>>>(w1, p_q1, w2, p_q2, NW / 4);

    // GEMM1: [M, 768] x [H, 768]^T -> gelu -> fp16 h
    {
        dim3 grid(HQ / 128, MQ / 64);
        hmma_gemm<1><<<grid, 128, SMEM_DYN>>>(
            p_xh, p_q1, b1, (void*)p_hh, MQ, HQ, DQ, 0);
    }
    // GEMM2: [M, 3072] x [D, 3072]^T -> + b2 -> out fp32
    {
        dim3 grid(DQ / 128, MQ / 64);
        hmma_gemm<0><<<grid, 128, SMEM_DYN>>>(
            p_hh, p_q2, b2, (void*)out, MQ, DQ, HQ, 1);
    }
}

// round 16
// speedup vs baseline: 1.0063x; 1.0063x over previous
#include <cuda_runtime.h>
#include <cuda_fp16.h>
#include <math.h>
#include <stdint.h>

// Problem shape (fixed by the reference)
#define BQ 64
#define SQ 197
#define DQ 768
#define HQ 3072
#define MQ (BQ * SQ)  // 12608 = 197 * 64  -> M-tiles of 64 are EXACT (no edge)

// ---------------------------------------------------------------------------
// Device global scratch (no allocation allowed)
// ---------------------------------------------------------------------------
__device__ __half g_xh [(size_t)MQ * DQ];   // x in fp16
__device__ __half g_hh [(size_t)MQ * HQ];   // h (post-GELU) in fp16
__device__ __half g_q1 [(size_t)HQ * DQ];   // ternary w1 in fp16 (exact)
__device__ __half g_q2 [(size_t)DQ * HQ];   // ternary w2 in fp16 (exact)
__device__ float g_partial[1024];
__device__ float g_gamma[2];

__device__ __forceinline__ uint32_t smem_u32(const void* p) {
    uint32_t a;
    asm("{ .reg .u64 t; cvta.to.shared.u64 t, %1; cvt.u32.u64 %0, t; }"
        : "=r"(a) : "l"(p));
    return a;
}

__device__ __forceinline__ uint32_t pack_h2(float a, float b) {
    __half2 p;
    p.x = __float2half_rn(a);
    p.y = __float2half_rn(b);
    return *(uint32_t*)&p;
}

// ---------------------------------------------------------------------------
// prep1: blocks 0-511 abs(w1), 512-1023 abs(w2), rest cvt x (MLP=4).
// ---------------------------------------------------------------------------
__global__ void prep1_kernel(const float* __restrict__ w1,
                             const float* __restrict__ w2, int nw,
                             const float* __restrict__ x,
                             __half* __restrict__ xh, int nx4) {
    int b = blockIdx.x;
    if (b < 1024) {
        const float* w = (b < 512) ? w1 : w2;
        int slot = (b < 512) ? 0 : 1;
        int rb = b & 511;
        __shared__ float sdata[256];
        float s = 0.0f;
        for (int i = rb * blockDim.x + threadIdx.x; i < nw;
             i += 512 * blockDim.x)
            s += fabsf(w[i]);
        sdata[threadIdx.x] = s;
        __syncthreads();
        #pragma unroll
        for (int off = 128; off > 0; off >>= 1) {
            if (threadIdx.x < off) sdata[threadIdx.x] += sdata[threadIdx.x + off];
            __syncthreads();
        }
        if (threadIdx.x == 0) g_partial[slot * 512 + rb] = sdata[0];
    } else {
        int base = (b - 1024) * 1024 + threadIdx.x;
        float4 v[4];
        int idx[4];
        #pragma unroll
        for (int u = 0; u < 4; u++) {
            idx[u] = base + u * 256;
            if (idx[u] < nx4) v[u] = ((const float4*)x)[idx[u]];
        }
        #pragma unroll
        for (int u = 0; u < 4; u++) {
            if (idx[u] < nx4) {
                uint2 st = make_uint2(pack_h2(v[u].x, v[u].y),
                                      pack_h2(v[u].z, v[u].w));
                ((uint2*)xh)[idx[u]] = st;
            }
        }
    }
}

__global__ void finalize_gamma_kernel(int n1, int n2) {
    __shared__ float sdata[512];
    int t = threadIdx.x;
    sdata[t] = g_partial[t];
    __syncthreads();
    #pragma unroll
    for (int off = 256; off > 0; off >>= 1) {
        if (t < off) sdata[t] += sdata[t + off];
        __syncthreads();
    }
    if (t == 0) g_gamma[0] = sdata[0] / (float)n1 + 1e-5f;
    __syncthreads();
    sdata[t] = g_partial[512 + t];
    __syncthreads();
    #pragma unroll
    for (int off = 256; off > 0; off >>= 1) {
        if (t < off) sdata[t] += sdata[t + off];
        __syncthreads();
    }
    if (t == 0) g_gamma[1] = sdata[0] / (float)n2 + 1e-5f;
}

// ternarize BOTH weights (MLP=4): blocks [0,576) -> w1, [576,1152) -> w2
__global__ void quant_both_kernel(const float* __restrict__ w1,
                                  __half* __restrict__ q1,
                                  const float* __restrict__ w2,
                                  __half* __restrict__ q2, int n4) {
    int b = blockIdx.x;
    const float* w;
    __half* q;
    int slot, rb;
    if (b < 576) { w = w1; q = q1; slot = 0; rb = b; }
    else         { w = w2; q = q2; slot = 1; rb = b - 576; }
    float inv = 1.0f / g_gamma[slot];
    int base = rb * 1024 + threadIdx.x;
    float4 v[4];
    int idx[4];
    #pragma unroll
    for (int u = 0; u < 4; u++) {
        idx[u] = base + u * 256;
        if (idx[u] < n4) v[u] = ((const float4*)w)[idx[u]];
    }
    #pragma unroll
    for (int u = 0; u < 4; u++) {
        if (idx[u] < n4) {
            float t0 = fminf(1.0f, fmaxf(-1.0f, rintf(v[u].x * inv)));
            float t1 = fminf(1.0f, fmaxf(-1.0f, rintf(v[u].y * inv)));
            float t2 = fminf(1.0f, fmaxf(-1.0f, rintf(v[u].z * inv)));
            float t3 = fminf(1.0f, fmaxf(-1.0f, rintf(v[u].w * inv)));
            uint2 st = make_uint2(pack_h2(t0, t1), pack_h2(t2, t3));
            ((uint2*)q)[idx[u]] = st;
        }
    }
}

// ---------------------------------------------------------------------------
// HMMA GEMM (R14 engine; ONLY change: M-edge predication stripped —
// M % 64 == 0 so the A-side guard and epilogue row-branch are dead code).
// 64x128 CTA tile, 128 threads (4 warps x 64x32), 4 CTAs/SM,
// analytic swizzle, double-buffered cp.async with runtime buf indexing (R14).
// ---------------------------------------------------------------------------
template <int GELU_H>
__global__ __launch_bounds__(128, 4)
void hmma_gemm(const __half* __restrict__ A,
               const __half* __restrict__ B,
               const float* __restrict__ bias,
               void* __restrict__ Cout,
               int M, int N, int K, int gslot) {
    extern __shared__ char smem[];
    const uint32_t sb = smem_u32(smem);
    const int tid  = threadIdx.x;
    const int wid  = tid >> 5;      // 0..3 -> n-block of 32
    const int lane = tid & 31;
    const int m0 = blockIdx.y * 64;
    const int n0 = blockIdx.x * 128;
    const int wn = wid;

    const int nch = K >> 6;    // chunks of 64 fp16

    const uint32_t preA = (uint32_t)((((lane >> 4) << 4) ^ ((lane & 7) << 4)));
    const uint32_t preB = (uint32_t)((((lane & 8) << 1) ^ ((lane & 7) << 4)));
    const uint32_t rowA = (uint32_t)(lane & 15) * 128u;
    const uint32_t rowB = (uint32_t)(wn * 32 + (lane & 7) + ((lane >> 4) << 3)) * 128u;

    float acc[4][4][4];
    #pragma unroll
    for (int i = 0; i < 4; i++)
        #pragma unroll
        for (int j = 0; j < 4; j++)
            #pragma unroll
            for (int k = 0; k < 4; k++) acc[i][j][k] = 0.0f;

    auto load_chunk = [&](int c) {
        const int buf = c & 1;
        const uint32_t offA = buf * 24576u;
        const uint32_t offB = offA + 8192u;
        const __half* Ag = A + (size_t)m0 * K + (size_t)c * 64;
        const __half* Bg = B + (size_t)n0 * K + (size_t)c * 64;
        #pragma unroll
        for (int t = 0; t < 4; t++) {          // A: 64 rows x 8 sixteens
            int idx = tid + t * 128;
            int row = idx >> 3;
            int c16 = idx & 7;
            uint32_t sw = (uint32_t)row * 128u
                        + (((uint32_t)c16 * 16u) ^ (((uint32_t)row & 7u) << 4));
            const void* ga = Ag + (size_t)row * K + c16 * 8;
            asm volatile("cp.async.cg.shared.global [%0], [%1], 16;"
                         :: "r"(sb + offA + sw), "l"(ga));
        }
        #pragma unroll
        for (int t = 0; t < 8; t++) {          // B: 128 rows x 8 sixteens
            int idx = tid + t * 128;
            int row = idx >> 3;
            int c16 = idx & 7;
            uint32_t sw = (uint32_t)row * 128u
                        + (((uint32_t)c16 * 16u) ^ (((uint32_t)row & 7u) << 4));
            const void* gb = Bg + (size_t)row * K + c16 * 8;
            asm volatile("cp.async.cg.shared.global [%0], [%1], 16;"
                         :: "r"(sb + offB + sw), "l"(gb));
        }
        asm volatile("cp.async.commit_group;" ::: "memory");
    };

    auto compute_chunk = [&](int buf) {
        const uint32_t baseA = sb + buf * 24576u + rowA;
        const uint32_t baseB = sb + buf * 24576u + 8192u + rowB;
        #pragma unroll
        for (int kk = 0; kk < 64; kk += 16) {
            const uint32_t cA = ((uint32_t)(2 * kk)) ^ preA;
            const uint32_t cB = ((uint32_t)(2 * kk)) ^ preB;
            uint32_t a[4][4];
            #pragma unroll
            for (int mi = 0; mi < 4; mi++) {
                asm volatile(
                    "ldmatrix.sync.aligned.m8n8.x4.shared.b16 {%0,%1,%2,%3}, [%4];"
                    : "=r"(a[mi][0]), "=r"(a[mi][1]), "=r"(a[mi][2]), "=r"(a[mi][3])
                    : "r"(baseA + (uint32_t)(mi * 2048) + cA));
            }
            uint32_t b[4][2];
            #pragma unroll
            for (int nj = 0; nj < 2; nj++) {
                uint32_t b0, b1, b2, b3;
                asm volatile(
                    "ldmatrix.sync.aligned.m8n8.x4.shared.b16 {%0,%1,%2,%3}, [%4];"
                    : "=r"(b0), "=r"(b1), "=r"(b2), "=r"(b3)
                    : "r"(baseB + (uint32_t)(nj * 2048) + cB));
                b[nj * 2 + 0][0] = b0; b[nj * 2 + 0][1] = b1;
                b[nj * 2 + 1][0] = b2; b[nj * 2 + 1][1] = b3;
            }
            #pragma unroll
            for (int mi = 0; mi < 4; mi++)
                #pragma unroll
                for (int ni = 0; ni < 4; ni++)
                    asm volatile(
                        "mma.sync.aligned.m16n8k16.row.col.f32.f16.f16.f32 "
                        "{%0,%1,%2,%3}, {%4,%5,%6,%7}, {%8,%9}, {%0,%1,%2,%3};"
                        : "+f"(acc[mi][ni][0]), "+f"(acc[mi][ni][1]),
                          "+f"(acc[mi][ni][2]), "+f"(acc[mi][ni][3])
                        : "r"(a[mi][0]), "r"(a[mi][1]), "r"(a[mi][2]), "r"(a[mi][3]),
                          "r"(b[ni][0]), "r"(b[ni][1]));
        }
    };

    load_chunk(0);
    for (int c = 0; c < nch; c++) {
        if (c + 1 < nch) {
            load_chunk(c + 1);
            asm volatile("cp.async.wait_group 1;" ::: "memory");
        } else {
            asm volatile("cp.async.wait_group 0;" ::: "memory");
        }
        __syncthreads();
        compute_chunk(c & 1);
        __syncthreads();
    }

    // ---- epilogue (branch-free: M % 64 == 0) ----
    const float gamma = g_gamma[gslot];
    #pragma unroll
    for (int mi = 0; mi < 4; mi++) {
        #pragma unroll
        for (int half = 0; half < 2; half++) {
            int gr = m0 + mi * 16 + (lane >> 2) + half * 8;
            #pragma unroll
            for (int ni = 0; ni < 4; ni++) {
                int gc = n0 + wn * 32 + ni * 8 + 2 * (lane & 3);
                float v0 = acc[mi][ni][half * 2 + 0] * gamma + bias[gc];
                float v1 = acc[mi][ni][half * 2 + 1] * gamma + bias[gc + 1];
                if (GELU_H) {
                    v0 = 0.5f * v0 * (1.0f + erff(v0 * 0.70710678118654752f));
                    v1 = 0.5f * v1 * (1.0f + erff(v1 * 0.70710678118654752f));
                    __half2 p;
                    p.x = __float2half_rn(v0);
                    p.y = __float2half_rn(v1);
                    *(__half2*)((__half*)Cout + (size_t)gr * N + gc) = p;
                } else {
                    *(float2*)((float*)Cout + (size_t)gr * N + gc) =
                        make_float2(v0, v1);
                }
            }
        }
    }
}

// ---------------------------------------------------------------------------
// Launch
// ---------------------------------------------------------------------------
extern "C" void kernel_launch(void* const* d_in, const int* in_sizes, int n_in,
                              void* d_out, int out_size) {
    const float* x  = (const float*)d_in[0];
    const float* w1 = (const float*)d_in[1];
    const float* b1 = (const float*)d_in[2];
    const float* w2 = (const float*)d_in[3];
    const float* b2 = (const float*)d_in[4];
    float* out = (float*)d_out;

    __half *p_xh, *p_hh, *p_q1, *p_q2;
    cudaGetSymbolAddress((void**)&p_xh, g_xh);
    cudaGetSymbolAddress((void**)&p_hh, g_hh);
    cudaGetSymbolAddress((void**)&p_q1, g_q1);
    cudaGetSymbolAddress((void**)&p_q2, g_q2);

    const int NW = HQ * DQ;          // 2359296
    const int NX4 = MQ * DQ / 4;     // 2420736 = 2364 * 1024
    const int SMEM_DYN = 2 * 24576;  // 48KB

    static bool attr_done = false;
    if (!attr_done) {
        cudaFuncSetAttribute(hmma_gemm<1>,
            cudaFuncAttributeMaxDynamicSharedMemorySize, SMEM_DYN);
        cudaFuncSetAttribute(hmma_gemm<0>,
            cudaFuncAttributeMaxDynamicSharedMemorySize, SMEM_DYN);
        attr_done = true;
    }

    prep1_kernel<<<1024 + NX4 / 1024, 256>>>(w1, w2, NW, x, p_xh, NX4);
    finalize_gamma_kernel<<<1, 512>>>(NW, NW);
    quant_both_kernel<<<1152, 256>>>(w1, p_q1, w2, p_q2, NW / 4);

    // GEMM1: [M, 768] x [H, 768]^T -> gelu -> fp16 h
    {
        dim3 grid(HQ / 128, MQ / 64);
        hmma_gemm<1><<<grid, 128, SMEM_DYN>>>(
            p_xh, p_q1, b1, (void*)p_hh, MQ, HQ, DQ, 0);
    }
    // GEMM2: [M, 3072] x [D, 3072]^T -> + b2 -> out fp32
    {
        dim3 grid(DQ / 128, MQ / 64);
        hmma_gemm<0><<<grid, 128, SMEM_DYN>>>(
            p_hh, p_q2, b2, (void*)out, MQ, DQ, HQ, 1);
    }
}

// round 17
// speedup vs baseline: 1.0190x; 1.0126x over previous
#include <cuda_runtime.h>
#include <cuda_fp16.h>
#include <math.h>
#include <stdint.h>

// Problem shape (fixed by the reference)
#define BQ 64
#define SQ 197
#define DQ 768
#define HQ 3072
#define MQ (BQ * SQ)  // 12608 = 197 * 64  -> M-tiles of 64 are EXACT (no edge)

// ---------------------------------------------------------------------------
// Device global scratch (no allocation allowed)
// ---------------------------------------------------------------------------
__device__ __half g_xh [(size_t)MQ * DQ];   // x in fp16
__device__ __half g_hh [(size_t)MQ * HQ];   // h (post-GELU) in fp16
__device__ __half g_q1 [(size_t)HQ * DQ];   // ternary w1 in fp16 (exact)
__device__ __half g_q2 [(size_t)DQ * HQ];   // ternary w2 in fp16 (exact)
__device__ float g_partial[1024];
__device__ float g_gamma[2];

__device__ __forceinline__ uint32_t smem_u32(const void* p) {
    uint32_t a;
    asm("{ .reg .u64 t; cvta.to.shared.u64 t, %1; cvt.u32.u64 %0, t; }"
        : "=r"(a) : "l"(p));
    return a;
}

__device__ __forceinline__ uint32_t pack_h2(float a, float b) {
    __half2 p;
    p.x = __float2half_rn(a);
    p.y = __float2half_rn(b);
    return *(uint32_t*)&p;
}

// ---------------------------------------------------------------------------
// prep1: blocks 0-511 abs(w1), 512-1023 abs(w2), rest cvt x (MLP=4).
// ---------------------------------------------------------------------------
__global__ void prep1_kernel(const float* __restrict__ w1,
                             const float* __restrict__ w2, int nw,
                             const float* __restrict__ x,
                             __half* __restrict__ xh, int nx4) {
    int b = blockIdx.x;
    if (b < 1024) {
        const float* w = (b < 512) ? w1 : w2;
        int slot = (b < 512) ? 0 : 1;
        int rb = b & 511;
        __shared__ float sdata[256];
        float s = 0.0f;
        for (int i = rb * blockDim.x + threadIdx.x; i < nw;
             i += 512 * blockDim.x)
            s += fabsf(w[i]);
        sdata[threadIdx.x] = s;
        __syncthreads();
        #pragma unroll
        for (int off = 128; off > 0; off >>= 1) {
            if (threadIdx.x < off) sdata[threadIdx.x] += sdata[threadIdx.x + off];
            __syncthreads();
        }
        if (threadIdx.x == 0) g_partial[slot * 512 + rb] = sdata[0];
    } else {
        int base = (b - 1024) * 1024 + threadIdx.x;
        float4 v[4];
        int idx[4];
        #pragma unroll
        for (int u = 0; u < 4; u++) {
            idx[u] = base + u * 256;
            if (idx[u] < nx4) v[u] = ((const float4*)x)[idx[u]];
        }
        #pragma unroll
        for (int u = 0; u < 4; u++) {
            if (idx[u] < nx4) {
                uint2 st = make_uint2(pack_h2(v[u].x, v[u].y),
                                      pack_h2(v[u].z, v[u].w));
                ((uint2*)xh)[idx[u]] = st;
            }
        }
    }
}

// ---------------------------------------------------------------------------
// quant_both: every block inline-reduces its slot's 512 partials to gamma
// (identical fixed tree in every block -> deterministic), then ternarizes
// its 1024-float4 slice (MLP=4). Blocks 0 / 576 publish g_gamma for the
// GEMM epilogues (GEMMs launch strictly after this kernel).
// ---------------------------------------------------------------------------
__global__ void quant_both_kernel(const float* __restrict__ w1,
                                  __half* __restrict__ q1,
                                  const float* __restrict__ w2,
                                  __half* __restrict__ q2,
                                  int n4, int nw) {
    int b = blockIdx.x;
    const float* w;
    __half* q;
    int slot, rb;
    if (b < 576) { w = w1; q = q1; slot = 0; rb = b; }
    else         { w = w2; q = q2; slot = 1; rb = b - 576; }

    // inline gamma: reduce g_partial[slot*512 .. +512)
    __shared__ float sdata[256];
    __shared__ float s_gamma;
    int t = threadIdx.x;
    sdata[t] = g_partial[slot * 512 + t] + g_partial[slot * 512 + 256 + t];
    __syncthreads();
    #pragma unroll
    for (int off = 128; off > 0; off >>= 1) {
        if (t < off) sdata[t] += sdata[t + off];
        __syncthreads();
    }
    if (t == 0) {
        float g = sdata[0] / (float)nw + 1e-5f;
        s_gamma = g;
        if (rb == 0) g_gamma[slot] = g;   // publish for GEMM epilogues
    }
    __syncthreads();
    float inv = 1.0f / s_gamma;

    int base = rb * 1024 + t;
    float4 v[4];
    int idx[4];
    #pragma unroll
    for (int u = 0; u < 4; u++) {
        idx[u] = base + u * 256;
        if (idx[u] < n4) v[u] = ((const float4*)w)[idx[u]];
    }
    #pragma unroll
    for (int u = 0; u < 4; u++) {
        if (idx[u] < n4) {
            float t0 = fminf(1.0f, fmaxf(-1.0f, rintf(v[u].x * inv)));
            float t1 = fminf(1.0f, fmaxf(-1.0f, rintf(v[u].y * inv)));
            float t2 = fminf(1.0f, fmaxf(-1.0f, rintf(v[u].z * inv)));
            float t3 = fminf(1.0f, fmaxf(-1.0f, rintf(v[u].w * inv)));
            uint2 st = make_uint2(pack_h2(t0, t1), pack_h2(t2, t3));
            ((uint2*)q)[idx[u]] = st;
        }
    }
}

// ---------------------------------------------------------------------------
// HMMA GEMM (converged engine): 64x128 CTA tile, 128 threads (4 warps x
// 64x32), 4 CTAs/SM, analytic swizzle, double-buffered cp.async,
// branch-free M (M % 64 == 0).
// ---------------------------------------------------------------------------
template <int GELU_H>
__global__ __launch_bounds__(128, 4)
void hmma_gemm(const __half* __restrict__ A,
               const __half* __restrict__ B,
               const float* __restrict__ bias,
               void* __restrict__ Cout,
               int M, int N, int K, int gslot) {
    extern __shared__ char smem[];
    const uint32_t sb = smem_u32(smem);
    const int tid  = threadIdx.x;
    const int wid  = tid >> 5;      // 0..3 -> n-block of 32
    const int lane = tid & 31;
    const int m0 = blockIdx.y * 64;
    const int n0 = blockIdx.x * 128;
    const int wn = wid;

    const int nch = K >> 6;    // chunks of 64 fp16

    const uint32_t preA = (uint32_t)((((lane >> 4) << 4) ^ ((lane & 7) << 4)));
    const uint32_t preB = (uint32_t)((((lane & 8) << 1) ^ ((lane & 7) << 4)));
    const uint32_t rowA = (uint32_t)(lane & 15) * 128u;
    const uint32_t rowB = (uint32_t)(wn * 32 + (lane & 7) + ((lane >> 4) << 3)) * 128u;

    float acc[4][4][4];
    #pragma unroll
    for (int i = 0; i < 4; i++)
        #pragma unroll
        for (int j = 0; j < 4; j++)
            #pragma unroll
            for (int k = 0; k < 4; k++) acc[i][j][k] = 0.0f;

    auto load_chunk = [&](int c) {
        const int buf = c & 1;
        const uint32_t offA = buf * 24576u;
        const uint32_t offB = offA + 8192u;
        const __half* Ag = A + (size_t)m0 * K + (size_t)c * 64;
        const __half* Bg = B + (size_t)n0 * K + (size_t)c * 64;
        #pragma unroll
        for (int t = 0; t < 4; t++) {          // A: 64 rows x 8 sixteens
            int idx = tid + t * 128;
            int row = idx >> 3;
            int c16 = idx & 7;
            uint32_t sw = (uint32_t)row * 128u
                        + (((uint32_t)c16 * 16u) ^ (((uint32_t)row & 7u) << 4));
            const void* ga = Ag + (size_t)row * K + c16 * 8;
            asm volatile("cp.async.cg.shared.global [%0], [%1], 16;"
                         :: "r"(sb + offA + sw), "l"(ga));
        }
        #pragma unroll
        for (int t = 0; t < 8; t++) {          // B: 128 rows x 8 sixteens
            int idx = tid + t * 128;
            int row = idx >> 3;
            int c16 = idx & 7;
            uint32_t sw = (uint32_t)row * 128u
                        + (((uint32_t)c16 * 16u) ^ (((uint32_t)row & 7u) << 4));
            const void* gb = Bg + (size_t)row * K + c16 * 8;
            asm volatile("cp.async.cg.shared.global [%0], [%1], 16;"
                         :: "r"(sb + offB + sw), "l"(gb));
        }
        asm volatile("cp.async.commit_group;" ::: "memory");
    };

    auto compute_chunk = [&](int buf) {
        const uint32_t baseA = sb + buf * 24576u + rowA;
        const uint32_t baseB = sb + buf * 24576u + 8192u + rowB;
        #pragma unroll
        for (int kk = 0; kk < 64; kk += 16) {
            const uint32_t cA = ((uint32_t)(2 * kk)) ^ preA;
            const uint32_t cB = ((uint32_t)(2 * kk)) ^ preB;
            uint32_t a[4][4];
            #pragma unroll
            for (int mi = 0; mi < 4; mi++) {
                asm volatile(
                    "ldmatrix.sync.aligned.m8n8.x4.shared.b16 {%0,%1,%2,%3}, [%4];"
                    : "=r"(a[mi][0]), "=r"(a[mi][1]), "=r"(a[mi][2]), "=r"(a[mi][3])
                    : "r"(baseA + (uint32_t)(mi * 2048) + cA));
            }
            uint32_t b[4][2];
            #pragma unroll
            for (int nj = 0; nj < 2; nj++) {
                uint32_t b0, b1, b2, b3;
                asm volatile(
                    "ldmatrix.sync.aligned.m8n8.x4.shared.b16 {%0,%1,%2,%3}, [%4];"
                    : "=r"(b0), "=r"(b1), "=r"(b2), "=r"(b3)
                    : "r"(baseB + (uint32_t)(nj * 2048) + cB));
                b[nj * 2 + 0][0] = b0; b[nj * 2 + 0][1] = b1;
                b[nj * 2 + 1][0] = b2; b[nj * 2 + 1][1] = b3;
            }
            #pragma unroll
            for (int mi = 0; mi < 4; mi++)
                #pragma unroll
                for (int ni = 0; ni < 4; ni++)
                    asm volatile(
                        "mma.sync.aligned.m16n8k16.row.col.f32.f16.f16.f32 "
                        "{%0,%1,%2,%3}, {%4,%5,%6,%7}, {%8,%9}, {%0,%1,%2,%3};"
                        : "+f"(acc[mi][ni][0]), "+f"(acc[mi][ni][1]),
                          "+f"(acc[mi][ni][2]), "+f"(acc[mi][ni][3])
                        : "r"(a[mi][0]), "r"(a[mi][1]), "r"(a[mi][2]), "r"(a[mi][3]),
                          "r"(b[ni][0]), "r"(b[ni][1]));
        }
    };

    load_chunk(0);
    for (int c = 0; c < nch; c++) {
        if (c + 1 < nch) {
            load_chunk(c + 1);
            asm volatile("cp.async.wait_group 1;" ::: "memory");
        } else {
            asm volatile("cp.async.wait_group 0;" ::: "memory");
        }
        __syncthreads();
        compute_chunk(c & 1);
        __syncthreads();
    }

    // ---- epilogue (branch-free: M % 64 == 0) ----
    const float gamma = g_gamma[gslot];
    #pragma unroll
    for (int mi = 0; mi < 4; mi++) {
        #pragma unroll
        for (int half = 0; half < 2; half++) {
            int gr = m0 + mi * 16 + (lane >> 2) + half * 8;
            #pragma unroll
            for (int ni = 0; ni < 4; ni++) {
                int gc = n0 + wn * 32 + ni * 8 + 2 * (lane & 3);
                float v0 = acc[mi][ni][half * 2 + 0] * gamma + bias[gc];
                float v1 = acc[mi][ni][half * 2 + 1] * gamma + bias[gc + 1];
                if (GELU_H) {
                    v0 = 0.5f * v0 * (1.0f + erff(v0 * 0.70710678118654752f));
                    v1 = 0.5f * v1 * (1.0f + erff(v1 * 0.70710678118654752f));
                    __half2 p;
                    p.x = __float2half_rn(v0);
                    p.y = __float2half_rn(v1);
                    *(__half2*)((__half*)Cout + (size_t)gr * N + gc) = p;
                } else {
                    *(float2*)((float*)Cout + (size_t)gr * N + gc) =
                        make_float2(v0, v1);
                }
            }
        }
    }
}

// ---------------------------------------------------------------------------
// Launch (4 launches: prep -> quant(+gamma) -> gemm1 -> gemm2)
// ---------------------------------------------------------------------------
extern "C" void kernel_launch(void* const* d_in, const int* in_sizes, int n_in,
                              void* d_out, int out_size) {
    const float* x  = (const float*)d_in[0];
    const float* w1 = (const float*)d_in[1];
    const float* b1 = (const float*)d_in[2];
    const float* w2 = (const float*)d_in[3];
    const float* b2 = (const float*)d_in[4];
    float* out = (float*)d_out;

    __half *p_xh, *p_hh, *p_q1, *p_q2;
    cudaGetSymbolAddress((void**)&p_xh, g_xh);
    cudaGetSymbolAddress((void**)&p_hh, g_hh);
    cudaGetSymbolAddress((void**)&p_q1, g_q1);
    cudaGetSymbolAddress((void**)&p_q2, g_q2);

    const int NW = HQ * DQ;          // 2359296
    const int NX4 = MQ * DQ / 4;     // 2420736 = 2364 * 1024
    const int SMEM_DYN = 2 * 24576;  // 48KB

    static bool attr_done = false;
    if (!attr_done) {
        cudaFuncSetAttribute(hmma_gemm<1>,
            cudaFuncAttributeMaxDynamicSharedMemorySize, SMEM_DYN);
        cudaFuncSetAttribute(hmma_gemm<0>,
            cudaFuncAttributeMaxDynamicSharedMemorySize, SMEM_DYN);
        attr_done = true;
    }

    prep1_kernel<<<1024 + NX4 / 1024, 256>>>(w1, w2, NW, x, p_xh, NX4);
    quant_both_kernel<<<1152, 256>>>(w1, p_q1, w2, p_q2, NW / 4, NW);

    // GEMM1: [M, 768] x [H, 768]^T -> gelu -> fp16 h
    {
        dim3 grid(HQ / 128, MQ / 64);
        hmma_gemm<1><<<grid, 128, SMEM_DYN>>>(
            p_xh, p_q1, b1, (void*)p_hh, MQ, HQ, DQ, 0);
    }
    // GEMM2: [M, 3072] x [D, 3072]^T -> + b2 -> out fp32
    {
        dim3 grid(DQ / 128, MQ / 64);
        hmma_gemm<0><<<grid, 128, SMEM_DYN>>>(
            p_hh, p_q2, b2, (void*)out, MQ, DQ, HQ, 1);
    }
}